// round 6
// baseline (speedup 1.0000x reference)
#include <cuda_runtime.h>
#include <math.h>

// Problem constants (GAT: N=50000 nodes, E=800000 edges, F_in=512, H=4, C=64, OUT=40)
#define F_IN   512
#define HC     256      // H*C for layer 1
#define NH     4
#define OUTC   40
#define MAXN   50000
#define MAXE   800000
#define MAXEDG (MAXE + MAXN)   // + self loops

#define NEG_INF __int_as_float(0xff800000u)

// ---------------- scratch (static device globals; no allocation allowed) ----
__device__ __align__(16) float g_h1[(size_t)MAXN * HC];   // x@W1
__device__ __align__(16) float g_h2[(size_t)MAXN * HC];   // layer1 output (post elu)
__device__ __align__(16) float g_h3[(size_t)MAXN * OUTC]; // h2@W2
__device__ float g_asrc1[MAXN * NH];
__device__ float g_adst1[MAXN * NH];
__device__ float g_asrc2[MAXN];
__device__ float g_adst2[MAXN];
__device__ int   g_deg[MAXN];
__device__ int   g_rowptr[MAXN + 1];
__device__ int   g_cursor[MAXN];
__device__ int   g_esrc[MAXEDG];
__device__ int   g_src32[MAXE];
__device__ int   g_dst32[MAXE];
__device__ int   g_is64;

// ---------------- edge dtype detection + normalization ---------------------
// JAX default x64-disabled mode makes "int64" edge_index actually int32.
// Detect at runtime: int32 pairs read as int64 give values ~hi*2^32 >> N.
__global__ void k_detect(const void* __restrict__ ei, int E, int N) {
    if (blockIdx.x == 0 && threadIdx.x == 0) {
        const long long* p = (const long long*)ei;
        int ok64 = 1;
        int n = E < 64 ? E : 64;
        for (int i = 0; i < n; i++) {
            long long v = p[i];
            if (v < 0 || v >= (long long)N) { ok64 = 0; break; }
        }
        g_is64 = ok64;
    }
}

__global__ void k_convert(const void* __restrict__ ei, int E, int N) {
    int i = blockIdx.x * blockDim.x + threadIdx.x;
    if (i >= E) return;
    int s, d;
    if (g_is64) {
        const long long* p = (const long long*)ei;
        s = (int)p[i];
        d = (int)p[E + i];
    } else {
        const int* p = (const int*)ei;
        s = p[i];
        d = p[E + i];
    }
    // clamp as insurance against any malformed index
    s = s < 0 ? 0 : (s >= N ? N - 1 : s);
    d = d < 0 ? 0 : (d >= N ? N - 1 : d);
    g_src32[i] = s;
    g_dst32[i] = d;
}

// ---------------- CSR build ------------------------------------------------
__global__ void k_init_deg(int n) {
    int i = blockIdx.x * blockDim.x + threadIdx.x;
    if (i < n) g_deg[i] = 1;   // self loop
}

__global__ void k_count(int E) {
    int i = blockIdx.x * blockDim.x + threadIdx.x;
    if (i < E) atomicAdd(&g_deg[g_dst32[i]], 1);
}

// single-block exclusive scan of g_deg -> g_rowptr (n up to 50000)
__global__ void k_scan(int n) {
    __shared__ int s[1024];
    int t = threadIdx.x;
    int chunk = (n + 1023) >> 10;
    int b = t * chunk;
    int e = min(b + chunk, n);
    int sum = 0;
    for (int i = b; i < e; i++) sum += g_deg[i];
    s[t] = sum;
    __syncthreads();
    for (int off = 1; off < 1024; off <<= 1) {
        int v = (t >= off) ? s[t - off] : 0;
        __syncthreads();
        s[t] += v;
        __syncthreads();
    }
    int run = (t == 0) ? 0 : s[t - 1];
    for (int i = b; i < e; i++) { g_rowptr[i] = run; run += g_deg[i]; }
    if (t == 1023) g_rowptr[n] = s[1023];
}

__global__ void k_selfloop(int n) {
    int i = blockIdx.x * blockDim.x + threadIdx.x;
    if (i < n) {
        int r = g_rowptr[i];
        g_esrc[r] = i;          // self loop placed first
        g_cursor[i] = r + 1;
    }
}

__global__ void k_scatter(int E) {
    int i = blockIdx.x * blockDim.x + threadIdx.x;
    if (i < E) {
        int d = g_dst32[i];
        int p = atomicAdd(&g_cursor[d], 1);
        g_esrc[p] = g_src32[i];
    }
}

// ---------------- GEMM1: h1[M x 256] = x[M x 512] @ W1[512 x 256] ----------
__global__ __launch_bounds__(256) void k_gemm1(const float* __restrict__ A,
                                               const float* __restrict__ B, int M) {
    __shared__ float As[16][128];
    __shared__ float Bs[16][128];
    int t = threadIdx.x;
    int tx = t & 15, ty = t >> 4;
    int bm = blockIdx.x * 128;
    int bn = blockIdx.y * 128;

    float acc[8][8];
#pragma unroll
    for (int i = 0; i < 8; i++)
#pragma unroll
        for (int j = 0; j < 8; j++) acc[i][j] = 0.f;

    for (int kt = 0; kt < F_IN; kt += 16) {
        // A tile: 128 rows x 16 k (512 float4, 2 per thread), transposed store
#pragma unroll
        for (int i = 0; i < 2; i++) {
            int idx = t + i * 256;
            int row = idx >> 2;
            int c4  = (idx & 3) * 4;
            float4 v = make_float4(0.f, 0.f, 0.f, 0.f);
            int gr = bm + row;
            if (gr < M) v = *(const float4*)(A + (size_t)gr * F_IN + kt + c4);
            As[c4 + 0][row] = v.x;
            As[c4 + 1][row] = v.y;
            As[c4 + 2][row] = v.z;
            As[c4 + 3][row] = v.w;
        }
        // B tile: 16 k x 128 cols (512 float4, 2 per thread)
#pragma unroll
        for (int i = 0; i < 2; i++) {
            int idx = t + i * 256;
            int br = idx >> 5;
            int bc = (idx & 31) * 4;
            *(float4*)&Bs[br][bc] =
                *(const float4*)(B + (size_t)(kt + br) * HC + bn + bc);
        }
        __syncthreads();
#pragma unroll
        for (int k = 0; k < 16; k++) {
            float4 a0 = *(float4*)&As[k][ty * 4];
            float4 a1 = *(float4*)&As[k][64 + ty * 4];
            float4 b0 = *(float4*)&Bs[k][tx * 4];
            float4 b1 = *(float4*)&Bs[k][64 + tx * 4];
            float av[8] = {a0.x, a0.y, a0.z, a0.w, a1.x, a1.y, a1.z, a1.w};
            float bv[8] = {b0.x, b0.y, b0.z, b0.w, b1.x, b1.y, b1.z, b1.w};
#pragma unroll
            for (int i = 0; i < 8; i++)
#pragma unroll
                for (int j = 0; j < 8; j++) acc[i][j] += av[i] * bv[j];
        }
        __syncthreads();
    }
#pragma unroll
    for (int i = 0; i < 8; i++) {
        int gr = bm + ((i < 4) ? (ty * 4 + i) : (64 + ty * 4 + i - 4));
        if (gr >= M) continue;
        float* op = g_h1 + (size_t)gr * HC + bn;
        *(float4*)(op + tx * 4)      = make_float4(acc[i][0], acc[i][1], acc[i][2], acc[i][3]);
        *(float4*)(op + 64 + tx * 4) = make_float4(acc[i][4], acc[i][5], acc[i][6], acc[i][7]);
    }
}

// ---------------- attention coefficients layer 1 ---------------------------
// warp per node; lane l covers cols [8l, 8l+8), head = l>>3
__global__ void k_attn1(const float* __restrict__ att_src,
                        const float* __restrict__ att_dst, int N) {
    int warp = (blockIdx.x * blockDim.x + threadIdx.x) >> 5;
    int lane = threadIdx.x & 31;
    if (warp >= N) return;
    const float4* hp = (const float4*)(g_h1 + (size_t)warp * HC);
    float4 h0 = hp[lane * 2], h1v = hp[lane * 2 + 1];
    int base = lane * 8;
    float4 s0 = *(const float4*)(att_src + base);
    float4 s1 = *(const float4*)(att_src + base + 4);
    float4 d0 = *(const float4*)(att_dst + base);
    float4 d1 = *(const float4*)(att_dst + base + 4);
    float ps = h0.x * s0.x + h0.y * s0.y + h0.z * s0.z + h0.w * s0.w
             + h1v.x * s1.x + h1v.y * s1.y + h1v.z * s1.z + h1v.w * s1.w;
    float pd = h0.x * d0.x + h0.y * d0.y + h0.z * d0.z + h0.w * d0.w
             + h1v.x * d1.x + h1v.y * d1.y + h1v.z * d1.z + h1v.w * d1.w;
#pragma unroll
    for (int o = 4; o; o >>= 1) {
        ps += __shfl_xor_sync(0xffffffffu, ps, o);
        pd += __shfl_xor_sync(0xffffffffu, pd, o);
    }
    if ((lane & 7) == 0) {
        int h = lane >> 3;
        g_asrc1[warp * NH + h] = ps;
        g_adst1[warp * NH + h] = pd;
    }
}

// ---------------- layer-1 aggregation: warp/node, online softmax -----------
__global__ void k_agg1(const float* __restrict__ b1, int N) {
    int node = (blockIdx.x * blockDim.x + threadIdx.x) >> 5;
    int lane = threadIdx.x & 31;
    if (node >= N) return;
    int head = lane >> 3;
    int start = g_rowptr[node], end = g_rowptr[node + 1];
    float ad = g_adst1[node * NH + head];
    float m = NEG_INF, d = 0.f;
    float acc[8];
#pragma unroll
    for (int j = 0; j < 8; j++) acc[j] = 0.f;

    for (int e = start; e < end; e++) {
        int s = g_esrc[e];
        float al = g_asrc1[s * NH + head] + ad;
        al = al > 0.f ? al : 0.2f * al;             // leaky_relu
        float mn = fmaxf(m, al);
        float sc = __expf(m - mn);                  // 0 on first edge
        float w  = __expf(al - mn);
        d = d * sc + w;
        const float4* hp = (const float4*)(g_h1 + (size_t)s * HC) + lane * 2;
        float4 v0 = hp[0], v1 = hp[1];
        acc[0] = acc[0] * sc + w * v0.x;
        acc[1] = acc[1] * sc + w * v0.y;
        acc[2] = acc[2] * sc + w * v0.z;
        acc[3] = acc[3] * sc + w * v0.w;
        acc[4] = acc[4] * sc + w * v1.x;
        acc[5] = acc[5] * sc + w * v1.y;
        acc[6] = acc[6] * sc + w * v1.z;
        acc[7] = acc[7] * sc + w * v1.w;
        m = mn;
    }
    float inv = 1.f / (d + 1e-16f);
    int col = lane * 8;
#pragma unroll
    for (int j = 0; j < 8; j++) {
        float v = acc[j] * inv + __ldg(b1 + col + j);
        acc[j] = v > 0.f ? v : (expf(v) - 1.f);     // elu
    }
    float4* op = (float4*)(g_h2 + (size_t)node * HC + col);
    op[0] = make_float4(acc[0], acc[1], acc[2], acc[3]);
    op[1] = make_float4(acc[4], acc[5], acc[6], acc[7]);
}

// ---------------- GEMM2: h3[M x 40] = h2[M x 256] @ W2[256 x 40] -----------
__global__ __launch_bounds__(256) void k_gemm2(const float* __restrict__ W2, int M) {
    __shared__ float hs[64][65];   // padded vs 32-bank stride-64 conflict
    __shared__ float ws[64][OUTC];
    int t = threadIdx.x;
    int bm = blockIdx.x * 64;
    int cg = t & 7;      // 8 col groups x 5 cols
    int rg = t >> 3;     // 32 row groups x 2 rows
    float acc[2][5];
#pragma unroll
    for (int r = 0; r < 2; r++)
#pragma unroll
        for (int j = 0; j < 5; j++) acc[r][j] = 0.f;

    for (int kt = 0; kt < HC; kt += 64) {
#pragma unroll
        for (int i = 0; i < 4; i++) {
            int idx = t + i * 256;
            int row = idx >> 4;
            int c4  = (idx & 15) * 4;
            float4 v = make_float4(0.f, 0.f, 0.f, 0.f);
            int gr = bm + row;
            if (gr < M) v = *(const float4*)(g_h2 + (size_t)gr * HC + kt + c4);
            hs[row][c4 + 0] = v.x;
            hs[row][c4 + 1] = v.y;
            hs[row][c4 + 2] = v.z;
            hs[row][c4 + 3] = v.w;
        }
#pragma unroll
        for (int i = 0; i < 10; i++) {
            int idx = t + i * 256;
            int kr = idx / OUTC;
            int c  = idx - kr * OUTC;
            ws[kr][c] = W2[(size_t)(kt + kr) * OUTC + c];
        }
        __syncthreads();
#pragma unroll
        for (int k = 0; k < 64; k++) {
            float h0 = hs[rg * 2][k];
            float h1v = hs[rg * 2 + 1][k];
#pragma unroll
            for (int j = 0; j < 5; j++) {
                float w = ws[k][cg * 5 + j];
                acc[0][j] += h0 * w;
                acc[1][j] += h1v * w;
            }
        }
        __syncthreads();
    }
#pragma unroll
    for (int r = 0; r < 2; r++) {
        int gr = bm + rg * 2 + r;
        if (gr >= M) continue;
#pragma unroll
        for (int j = 0; j < 5; j++)
            g_h3[(size_t)gr * OUTC + cg * 5 + j] = acc[r][j];
    }
}

// ---------------- attention coefficients layer 2 ---------------------------
__global__ void k_attn2(const float* __restrict__ att_src,
                        const float* __restrict__ att_dst, int N) {
    int node = (blockIdx.x * blockDim.x + threadIdx.x) >> 5;
    int lane = threadIdx.x & 31;
    if (node >= N) return;
    const float* hp = g_h3 + (size_t)node * OUTC;
    float ps = hp[lane] * __ldg(att_src + lane);
    float pd = hp[lane] * __ldg(att_dst + lane);
    if (lane < 8) {
        ps += hp[32 + lane] * __ldg(att_src + 32 + lane);
        pd += hp[32 + lane] * __ldg(att_dst + 32 + lane);
    }
#pragma unroll
    for (int o = 16; o; o >>= 1) {
        ps += __shfl_xor_sync(0xffffffffu, ps, o);
        pd += __shfl_xor_sync(0xffffffffu, pd, o);
    }
    if (lane == 0) { g_asrc2[node] = ps; g_adst2[node] = pd; }
}

// ---------------- layer-2 aggregation + bias + log_softmax -----------------
__global__ void k_agg2(const float* __restrict__ b2, float* __restrict__ out, int N) {
    int node = (blockIdx.x * blockDim.x + threadIdx.x) >> 5;
    int lane = threadIdx.x & 31;
    if (node >= N) return;
    int start = g_rowptr[node], end = g_rowptr[node + 1];
    float ad = g_adst2[node];
    float m = NEG_INF, d = 0.f;
    float a0 = 0.f, a1 = 0.f;
    for (int e = start; e < end; e++) {
        int s = g_esrc[e];
        float al = g_asrc2[s] + ad;
        al = al > 0.f ? al : 0.2f * al;
        float mn = fmaxf(m, al);
        float sc = __expf(m - mn);
        float w  = __expf(al - mn);
        d = d * sc + w;
        const float* hp = g_h3 + (size_t)s * OUTC;
        float v0 = hp[lane];
        float v1 = (lane < 8) ? hp[32 + lane] : 0.f;
        a0 = a0 * sc + w * v0;
        a1 = a1 * sc + w * v1;
        m = mn;
    }
    float inv = 1.f / (d + 1e-16f);
    float o0 = a0 * inv + __ldg(b2 + lane);
    float o1 = (lane < 8) ? (a1 * inv + __ldg(b2 + 32 + lane)) : NEG_INF;
    // log_softmax over the node's 40 values
    float mx = fmaxf(o0, o1);
#pragma unroll
    for (int o = 16; o; o >>= 1) mx = fmaxf(mx, __shfl_xor_sync(0xffffffffu, mx, o));
    float se = expf(o0 - mx) + ((lane < 8) ? expf(o1 - mx) : 0.f);
#pragma unroll
    for (int o = 16; o; o >>= 1) se += __shfl_xor_sync(0xffffffffu, se, o);
    float L = logf(se);
    float* op = out + (size_t)node * OUTC;
    op[lane] = o0 - mx - L;
    if (lane < 8) op[32 + lane] = o1 - mx - L;
}

// ---------------- launch ----------------------------------------------------
extern "C" void kernel_launch(void* const* d_in, const int* in_sizes, int n_in,
                              void* d_out, int out_size) {
    const float* x   = (const float*)d_in[0];
    const void*  ei  = d_in[1];
    const float* W1  = (const float*)d_in[2];
    const float* as1 = (const float*)d_in[3];
    const float* ad1 = (const float*)d_in[4];
    const float* b1  = (const float*)d_in[5];
    const float* W2  = (const float*)d_in[6];
    const float* as2 = (const float*)d_in[7];
    const float* ad2 = (const float*)d_in[8];
    const float* b2  = (const float*)d_in[9];
    float*       out = (float*)d_out;

    int N = in_sizes[0] / F_IN;
    int E = in_sizes[1] / 2;

    int nb = (N + 255) / 256;
    int eb = (E + 255) / 256;
    int wb = (N + 7) / 8;   // one warp per node, 8 warps per block

    // Edge dtype normalization + CSR by destination (self loops included)
    k_detect<<<1, 32>>>(ei, E, N);
    k_convert<<<eb, 256>>>(ei, E, N);
    k_init_deg<<<nb, 256>>>(N);
    k_count<<<eb, 256>>>(E);
    k_scan<<<1, 1024>>>(N);
    k_selfloop<<<nb, 256>>>(N);
    k_scatter<<<eb, 256>>>(E);

    // Layer 1
    dim3 g1((N + 127) / 128, HC / 128);
    k_gemm1<<<g1, 256>>>(x, W1, N);
    k_attn1<<<wb, 256>>>(as1, ad1, N);
    k_agg1<<<wb, 256>>>(b1, N);

    // Layer 2
    k_gemm2<<<(N + 63) / 64, 256>>>(W2, N);
    k_attn2<<<wb, 256>>>(as2, ad2, N);
    k_agg2<<<wb, 256>>>(b2, out, N);
}

// round 9
// speedup vs baseline: 1.0455x; 1.0455x over previous
#include <cuda_runtime.h>
#include <math.h>

// Problem constants (GAT: N=50000 nodes, E=800000 edges, F_in=512, H=4, C=64, OUT=40)
#define F_IN   512
#define HC     256      // H*C for layer 1
#define NH     4
#define OUTC   40
#define MAXN   50000
#define MAXE   800000
#define MAXEDG (MAXE + MAXN)   // + self loops

#define NEG_INF __int_as_float(0xff800000u)

// ---------------- scratch (static device globals; no allocation allowed) ----
__device__ __align__(16) float g_h1[(size_t)MAXN * HC];   // x@W1
__device__ __align__(16) float g_h2[(size_t)MAXN * HC];   // layer1 output (post elu)
__device__ __align__(16) float g_h3[(size_t)MAXN * OUTC]; // h2@W2
__device__ float g_asrc1[MAXN * NH];
__device__ float g_adst1[MAXN * NH];
__device__ float g_asrc2[MAXN];
__device__ float g_adst2[MAXN];
__device__ int   g_deg[MAXN];
__device__ int   g_rowptr[MAXN + 1];
__device__ int   g_cursor[MAXN];
__device__ int   g_esrc[MAXEDG];
__device__ int   g_src32[MAXE];
__device__ int   g_dst32[MAXE];
__device__ int   g_is64;

// ---------------- edge dtype detection + normalization ---------------------
__global__ void k_detect(const void* __restrict__ ei, int E, int N) {
    if (blockIdx.x == 0 && threadIdx.x == 0) {
        const long long* p = (const long long*)ei;
        int ok64 = 1;
        int n = E < 64 ? E : 64;
        for (int i = 0; i < n; i++) {
            long long v = p[i];
            if (v < 0 || v >= (long long)N) { ok64 = 0; break; }
        }
        g_is64 = ok64;
    }
}

__global__ void k_convert(const void* __restrict__ ei, int E, int N) {
    int i = blockIdx.x * blockDim.x + threadIdx.x;
    if (i >= E) return;
    int s, d;
    if (g_is64) {
        const long long* p = (const long long*)ei;
        s = (int)p[i];
        d = (int)p[E + i];
    } else {
        const int* p = (const int*)ei;
        s = p[i];
        d = p[E + i];
    }
    s = s < 0 ? 0 : (s >= N ? N - 1 : s);
    d = d < 0 ? 0 : (d >= N ? N - 1 : d);
    g_src32[i] = s;
    g_dst32[i] = d;
}

// ---------------- CSR build ------------------------------------------------
__global__ void k_init_deg(int n) {
    int i = blockIdx.x * blockDim.x + threadIdx.x;
    if (i < n) g_deg[i] = 1;   // self loop
}

__global__ void k_count(int E) {
    int i = blockIdx.x * blockDim.x + threadIdx.x;
    if (i < E) atomicAdd(&g_deg[g_dst32[i]], 1);
}

__global__ void k_scan(int n) {
    __shared__ int s[1024];
    int t = threadIdx.x;
    int chunk = (n + 1023) >> 10;
    int b = t * chunk;
    int e = min(b + chunk, n);
    int sum = 0;
    for (int i = b; i < e; i++) sum += g_deg[i];
    s[t] = sum;
    __syncthreads();
    for (int off = 1; off < 1024; off <<= 1) {
        int v = (t >= off) ? s[t - off] : 0;
        __syncthreads();
        s[t] += v;
        __syncthreads();
    }
    int run = (t == 0) ? 0 : s[t - 1];
    for (int i = b; i < e; i++) { g_rowptr[i] = run; run += g_deg[i]; }
    if (t == 1023) g_rowptr[n] = s[1023];
}

__global__ void k_selfloop(int n) {
    int i = blockIdx.x * blockDim.x + threadIdx.x;
    if (i < n) {
        int r = g_rowptr[i];
        g_esrc[r] = i;          // self loop placed first
        g_cursor[i] = r + 1;
    }
}

__global__ void k_scatter(int E) {
    int i = blockIdx.x * blockDim.x + threadIdx.x;
    if (i < E) {
        int d = g_dst32[i];
        int p = atomicAdd(&g_cursor[d], 1);
        g_esrc[p] = g_src32[i];
    }
}

// ---------------- GEMM1 on tensor cores: 3xTF32 compensated ----------------
// h1[M x 256] = x[M x 512] @ W1[512 x 256], fp32-accurate via a=a_hi+a_lo split.
__device__ __forceinline__ unsigned f2tf(float f) {
    unsigned r;
    asm("cvt.rna.tf32.f32 %0, %1;" : "=r"(r) : "f"(f));
    return r;
}

__device__ __forceinline__ void mma8(float4& c, unsigned a0, unsigned a1,
                                     unsigned a2, unsigned a3,
                                     unsigned b0, unsigned b1) {
    asm volatile(
        "mma.sync.aligned.m16n8k8.row.col.f32.tf32.tf32.f32 "
        "{%0,%1,%2,%3}, {%4,%5,%6,%7}, {%8,%9}, {%0,%1,%2,%3};"
        : "+f"(c.x), "+f"(c.y), "+f"(c.z), "+f"(c.w)
        : "r"(a0), "r"(a1), "r"(a2), "r"(a3), "r"(b0), "r"(b1));
}

#define PITCH 136   // smem pitch in words: fragment gathers conflict-free

__global__ __launch_bounds__(256) void k_gemm1_tc(const float* __restrict__ A,
                                                  const float* __restrict__ B, int M) {
    __shared__ unsigned As_hi[16][PITCH];
    __shared__ unsigned As_lo[16][PITCH];
    __shared__ unsigned Bs_hi[16][PITCH];
    __shared__ unsigned Bs_lo[16][PITCH];

    int t    = threadIdx.x;
    int warp = t >> 5, lane = t & 31;
    int wm   = (warp >> 2) * 64;     // warp M offset (2 warps in M)
    int wn   = (warp & 3) * 32;      // warp N offset (4 warps in N)
    int gq   = lane >> 2;            // group id 0..7
    int tq   = lane & 3;             // thread-in-group 0..3
    int bm   = blockIdx.x * 128;
    int bn   = blockIdx.y * 128;

    float4 acc[4][4];
#pragma unroll
    for (int i = 0; i < 4; i++)
#pragma unroll
        for (int j = 0; j < 4; j++) acc[i][j] = make_float4(0.f, 0.f, 0.f, 0.f);

    for (int kt = 0; kt < F_IN; kt += 16) {
        // A tile 128 rows x 16 k, split hi/lo, stored k-major
#pragma unroll
        for (int i = 0; i < 2; i++) {
            int idx = t + i * 256;
            int row = idx >> 2;
            int c4  = (idx & 3) * 4;
            float4 v = make_float4(0.f, 0.f, 0.f, 0.f);
            int gr = bm + row;
            if (gr < M) v = *(const float4*)(A + (size_t)gr * F_IN + kt + c4);
            float vv[4] = {v.x, v.y, v.z, v.w};
#pragma unroll
            for (int j = 0; j < 4; j++) {
                unsigned hi = f2tf(vv[j]);
                As_hi[c4 + j][row] = hi;
                As_lo[c4 + j][row] = f2tf(vv[j] - __uint_as_float(hi));
            }
        }
        // B tile 16 k x 128 cols, split hi/lo (row-contiguous, float4-wide)
#pragma unroll
        for (int i = 0; i < 2; i++) {
            int idx = t + i * 256;
            int br = idx >> 5;
            int bc = (idx & 31) * 4;
            float4 v = *(const float4*)(B + (size_t)(kt + br) * HC + bn + bc);
            uint4 hi, lo;
            hi.x = f2tf(v.x); lo.x = f2tf(v.x - __uint_as_float(hi.x));
            hi.y = f2tf(v.y); lo.y = f2tf(v.y - __uint_as_float(hi.y));
            hi.z = f2tf(v.z); lo.z = f2tf(v.z - __uint_as_float(hi.z));
            hi.w = f2tf(v.w); lo.w = f2tf(v.w - __uint_as_float(hi.w));
            *(uint4*)&Bs_hi[br][bc] = hi;
            *(uint4*)&Bs_lo[br][bc] = lo;
        }
        __syncthreads();

#pragma unroll
        for (int s = 0; s < 2; s++) {
            int k0 = s * 8;
            unsigned ah[4][4], al[4][4], bh[4][2], bl[4][2];
#pragma unroll
            for (int mi = 0; mi < 4; mi++) {
                int m = wm + mi * 16 + gq;
                ah[mi][0] = As_hi[k0 + tq][m];
                ah[mi][1] = As_hi[k0 + tq][m + 8];
                ah[mi][2] = As_hi[k0 + tq + 4][m];
                ah[mi][3] = As_hi[k0 + tq + 4][m + 8];
                al[mi][0] = As_lo[k0 + tq][m];
                al[mi][1] = As_lo[k0 + tq][m + 8];
                al[mi][2] = As_lo[k0 + tq + 4][m];
                al[mi][3] = As_lo[k0 + tq + 4][m + 8];
            }
#pragma unroll
            for (int nj = 0; nj < 4; nj++) {
                int n = wn + nj * 8 + gq;
                bh[nj][0] = Bs_hi[k0 + tq][n];
                bh[nj][1] = Bs_hi[k0 + tq + 4][n];
                bl[nj][0] = Bs_lo[k0 + tq][n];
                bl[nj][1] = Bs_lo[k0 + tq + 4][n];
            }
#pragma unroll
            for (int mi = 0; mi < 4; mi++)
#pragma unroll
                for (int nj = 0; nj < 4; nj++) {
                    mma8(acc[mi][nj], ah[mi][0], ah[mi][1], ah[mi][2], ah[mi][3],
                         bl[nj][0], bl[nj][1]);                     // hi*lo
                    mma8(acc[mi][nj], al[mi][0], al[mi][1], al[mi][2], al[mi][3],
                         bh[nj][0], bh[nj][1]);                     // lo*hi
                    mma8(acc[mi][nj], ah[mi][0], ah[mi][1], ah[mi][2], ah[mi][3],
                         bh[nj][0], bh[nj][1]);                     // hi*hi
                }
        }
        __syncthreads();
    }

    // epilogue: c0 (row g, col 2tq), c1 (+1), c2 (row g+8), c3 (+1)
#pragma unroll
    for (int mi = 0; mi < 4; mi++) {
        int row0 = bm + wm + mi * 16 + gq;
        int row1 = row0 + 8;
#pragma unroll
        for (int nj = 0; nj < 4; nj++) {
            int col = bn + wn + nj * 8 + tq * 2;
            if (row0 < M)
                *(float2*)(g_h1 + (size_t)row0 * HC + col) =
                    make_float2(acc[mi][nj].x, acc[mi][nj].y);
            if (row1 < M)
                *(float2*)(g_h1 + (size_t)row1 * HC + col) =
                    make_float2(acc[mi][nj].z, acc[mi][nj].w);
        }
    }
}

// ---------------- attention coefficients layer 1 ---------------------------
__global__ void k_attn1(const float* __restrict__ att_src,
                        const float* __restrict__ att_dst, int N) {
    int warp = (blockIdx.x * blockDim.x + threadIdx.x) >> 5;
    int lane = threadIdx.x & 31;
    if (warp >= N) return;
    const float4* hp = (const float4*)(g_h1 + (size_t)warp * HC);
    float4 h0 = hp[lane * 2], h1v = hp[lane * 2 + 1];
    int base = lane * 8;
    float4 s0 = *(const float4*)(att_src + base);
    float4 s1 = *(const float4*)(att_src + base + 4);
    float4 d0 = *(const float4*)(att_dst + base);
    float4 d1 = *(const float4*)(att_dst + base + 4);
    float ps = h0.x * s0.x + h0.y * s0.y + h0.z * s0.z + h0.w * s0.w
             + h1v.x * s1.x + h1v.y * s1.y + h1v.z * s1.z + h1v.w * s1.w;
    float pd = h0.x * d0.x + h0.y * d0.y + h0.z * d0.z + h0.w * d0.w
             + h1v.x * d1.x + h1v.y * d1.y + h1v.z * d1.z + h1v.w * d1.w;
#pragma unroll
    for (int o = 4; o; o >>= 1) {
        ps += __shfl_xor_sync(0xffffffffu, ps, o);
        pd += __shfl_xor_sync(0xffffffffu, pd, o);
    }
    if ((lane & 7) == 0) {
        int h = lane >> 3;
        g_asrc1[warp * NH + h] = ps;
        g_adst1[warp * NH + h] = pd;
    }
}

// ---------------- layer-1 aggregation: warp/node, online softmax -----------
__global__ void k_agg1(const float* __restrict__ b1, int N) {
    int node = (blockIdx.x * blockDim.x + threadIdx.x) >> 5;
    int lane = threadIdx.x & 31;
    if (node >= N) return;
    int head = lane >> 3;
    int start = g_rowptr[node], end = g_rowptr[node + 1];
    float ad = g_adst1[node * NH + head];
    float m = NEG_INF, d = 0.f;
    float acc[8];
#pragma unroll
    for (int j = 0; j < 8; j++) acc[j] = 0.f;

    for (int e = start; e < end; e++) {
        int s = g_esrc[e];
        float al = g_asrc1[s * NH + head] + ad;
        al = al > 0.f ? al : 0.2f * al;             // leaky_relu
        float mn = fmaxf(m, al);
        float sc = __expf(m - mn);                  // 0 on first edge
        float w  = __expf(al - mn);
        d = d * sc + w;
        const float4* hp = (const float4*)(g_h1 + (size_t)s * HC) + lane * 2;
        float4 v0 = hp[0], v1 = hp[1];
        acc[0] = acc[0] * sc + w * v0.x;
        acc[1] = acc[1] * sc + w * v0.y;
        acc[2] = acc[2] * sc + w * v0.z;
        acc[3] = acc[3] * sc + w * v0.w;
        acc[4] = acc[4] * sc + w * v1.x;
        acc[5] = acc[5] * sc + w * v1.y;
        acc[6] = acc[6] * sc + w * v1.z;
        acc[7] = acc[7] * sc + w * v1.w;
        m = mn;
    }
    float inv = 1.f / (d + 1e-16f);
    int col = lane * 8;
#pragma unroll
    for (int j = 0; j < 8; j++) {
        float v = acc[j] * inv + __ldg(b1 + col + j);
        acc[j] = v > 0.f ? v : (expf(v) - 1.f);     // elu
    }
    float4* op = (float4*)(g_h2 + (size_t)node * HC + col);
    op[0] = make_float4(acc[0], acc[1], acc[2], acc[3]);
    op[1] = make_float4(acc[4], acc[5], acc[6], acc[7]);
}

// ---------------- GEMM2: h3[M x 40] = h2[M x 256] @ W2[256 x 40] -----------
__global__ __launch_bounds__(256) void k_gemm2(const float* __restrict__ W2, int M) {
    __shared__ float hs[64][65];
    __shared__ float ws[64][OUTC];
    int t = threadIdx.x;
    int bm = blockIdx.x * 64;
    int cg = t & 7;
    int rg = t >> 3;
    float acc[2][5];
#pragma unroll
    for (int r = 0; r < 2; r++)
#pragma unroll
        for (int j = 0; j < 5; j++) acc[r][j] = 0.f;

    for (int kt = 0; kt < HC; kt += 64) {
#pragma unroll
        for (int i = 0; i < 4; i++) {
            int idx = t + i * 256;
            int row = idx >> 4;
            int c4  = (idx & 15) * 4;
            float4 v = make_float4(0.f, 0.f, 0.f, 0.f);
            int gr = bm + row;
            if (gr < M) v = *(const float4*)(g_h2 + (size_t)gr * HC + kt + c4);
            hs[row][c4 + 0] = v.x;
            hs[row][c4 + 1] = v.y;
            hs[row][c4 + 2] = v.z;
            hs[row][c4 + 3] = v.w;
        }
#pragma unroll
        for (int i = 0; i < 10; i++) {
            int idx = t + i * 256;
            int kr = idx / OUTC;
            int c  = idx - kr * OUTC;
            ws[kr][c] = W2[(size_t)(kt + kr) * OUTC + c];
        }
        __syncthreads();
#pragma unroll
        for (int k = 0; k < 64; k++) {
            float h0 = hs[rg * 2][k];
            float h1v = hs[rg * 2 + 1][k];
#pragma unroll
            for (int j = 0; j < 5; j++) {
                float w = ws[k][cg * 5 + j];
                acc[0][j] += h0 * w;
                acc[1][j] += h1v * w;
            }
        }
        __syncthreads();
    }
#pragma unroll
    for (int r = 0; r < 2; r++) {
        int gr = bm + rg * 2 + r;
        if (gr >= M) continue;
#pragma unroll
        for (int j = 0; j < 5; j++)
            g_h3[(size_t)gr * OUTC + cg * 5 + j] = acc[r][j];
    }
}

// ---------------- attention coefficients layer 2 ---------------------------
__global__ void k_attn2(const float* __restrict__ att_src,
                        const float* __restrict__ att_dst, int N) {
    int node = (blockIdx.x * blockDim.x + threadIdx.x) >> 5;
    int lane = threadIdx.x & 31;
    if (node >= N) return;
    const float* hp = g_h3 + (size_t)node * OUTC;
    float ps = hp[lane] * __ldg(att_src + lane);
    float pd = hp[lane] * __ldg(att_dst + lane);
    if (lane < 8) {
        ps += hp[32 + lane] * __ldg(att_src + 32 + lane);
        pd += hp[32 + lane] * __ldg(att_dst + 32 + lane);
    }
#pragma unroll
    for (int o = 16; o; o >>= 1) {
        ps += __shfl_xor_sync(0xffffffffu, ps, o);
        pd += __shfl_xor_sync(0xffffffffu, pd, o);
    }
    if (lane == 0) { g_asrc2[node] = ps; g_adst2[node] = pd; }
}

// ---------------- layer-2 aggregation + bias + log_softmax -----------------
__global__ void k_agg2(const float* __restrict__ b2, float* __restrict__ out, int N) {
    int node = (blockIdx.x * blockDim.x + threadIdx.x) >> 5;
    int lane = threadIdx.x & 31;
    if (node >= N) return;
    int start = g_rowptr[node], end = g_rowptr[node + 1];
    float ad = g_adst2[node];
    float m = NEG_INF, d = 0.f;
    float a0 = 0.f, a1 = 0.f;
    for (int e = start; e < end; e++) {
        int s = g_esrc[e];
        float al = g_asrc2[s] + ad;
        al = al > 0.f ? al : 0.2f * al;
        float mn = fmaxf(m, al);
        float sc = __expf(m - mn);
        float w  = __expf(al - mn);
        d = d * sc + w;
        const float* hp = g_h3 + (size_t)s * OUTC;
        float v0 = hp[lane];
        float v1 = (lane < 8) ? hp[32 + lane] : 0.f;
        a0 = a0 * sc + w * v0;
        a1 = a1 * sc + w * v1;
        m = mn;
    }
    float inv = 1.f / (d + 1e-16f);
    float o0 = a0 * inv + __ldg(b2 + lane);
    float o1 = (lane < 8) ? (a1 * inv + __ldg(b2 + 32 + lane)) : NEG_INF;
    float mx = fmaxf(o0, o1);
#pragma unroll
    for (int o = 16; o; o >>= 1) mx = fmaxf(mx, __shfl_xor_sync(0xffffffffu, mx, o));
    float se = expf(o0 - mx) + ((lane < 8) ? expf(o1 - mx) : 0.f);
#pragma unroll
    for (int o = 16; o; o >>= 1) se += __shfl_xor_sync(0xffffffffu, se, o);
    float L = logf(se);
    float* op = out + (size_t)node * OUTC;
    op[lane] = o0 - mx - L;
    if (lane < 8) op[32 + lane] = o1 - mx - L;
}

// ---------------- launch ----------------------------------------------------
extern "C" void kernel_launch(void* const* d_in, const int* in_sizes, int n_in,
                              void* d_out, int out_size) {
    const float* x   = (const float*)d_in[0];
    const void*  ei  = d_in[1];
    const float* W1  = (const float*)d_in[2];
    const float* as1 = (const float*)d_in[3];
    const float* ad1 = (const float*)d_in[4];
    const float* b1  = (const float*)d_in[5];
    const float* W2  = (const float*)d_in[6];
    const float* as2 = (const float*)d_in[7];
    const float* ad2 = (const float*)d_in[8];
    const float* b2  = (const float*)d_in[9];
    float*       out = (float*)d_out;

    int N = in_sizes[0] / F_IN;
    int E = in_sizes[1] / 2;

    int nb = (N + 255) / 256;
    int eb = (E + 255) / 256;
    int wb = (N + 7) / 8;   // one warp per node, 8 warps per block

    // Edge dtype normalization + CSR by destination (self loops included)
    k_detect<<<1, 32>>>(ei, E, N);
    k_convert<<<eb, 256>>>(ei, E, N);
    k_init_deg<<<nb, 256>>>(N);
    k_count<<<eb, 256>>>(E);
    k_scan<<<1, 1024>>>(N);
    k_selfloop<<<nb, 256>>>(N);
    k_scatter<<<eb, 256>>>(E);

    // Layer 1
    dim3 g1((N + 127) / 128, HC / 128);
    k_gemm1_tc<<<g1, 256>>>(x, W1, N);
    k_attn1<<<wb, 256>>>(as1, ad1, N);
    k_agg1<<<wb, 256>>>(b1, N);

    // Layer 2
    k_gemm2<<<(N + 63) / 64, 256>>>(W2, N);
    k_attn2<<<wb, 256>>>(as2, ad2, N);
    k_agg2<<<wb, 256>>>(b2, out, N);
}

// round 14
// speedup vs baseline: 1.3127x; 1.2556x over previous
#include <cuda_runtime.h>
#include <math.h>
#include <stdint.h>

// Problem constants (GAT: N=50000 nodes, E=800000 edges, F_in=512, H=4, C=64, OUT=40)
#define F_IN   512
#define HC     256      // H*C for layer 1
#define NH     4
#define OUTC   40
#define MAXN   50000
#define MAXE   800000
#define MAXEDG (MAXE + MAXN)   // + self loops

#define NEG_INF __int_as_float(0xff800000u)

// ---------------- scratch (static device globals; no allocation allowed) ----
__device__ __align__(16) float g_h1[(size_t)MAXN * HC];   // x@W1
__device__ __align__(16) float g_h2[(size_t)MAXN * HC];   // layer1 output (post elu)
__device__ __align__(16) float g_h3[(size_t)MAXN * OUTC]; // h2@W2
__device__ float g_asrc1[MAXN * NH];
__device__ float g_adst1[MAXN * NH];
__device__ float g_asrc2[MAXN];
__device__ float g_adst2[MAXN];
__device__ int   g_deg[MAXN];
__device__ int   g_rowptr[MAXN + 1];
__device__ int   g_cursor[MAXN];
__device__ int   g_esrc[MAXEDG];
__device__ int   g_src32[MAXE];
__device__ int   g_dst32[MAXE];
__device__ int   g_is64;
// W1 pre-split to bf16 hi/lo, transposed to [n][k]; reinterpreted as packed
// bf16x2 words (word w = k-pair {2w, 2w+1}) for the MMA B operand.
__device__ __align__(16) unsigned short g_w1hi[(size_t)HC * F_IN];
__device__ __align__(16) unsigned short g_w1lo[(size_t)HC * F_IN];

// ---------------- edge dtype detection + normalization ---------------------
__global__ void k_detect(const void* __restrict__ ei, int E, int N) {
    if (blockIdx.x == 0 && threadIdx.x == 0) {
        const long long* p = (const long long*)ei;
        int ok64 = 1;
        int n = E < 64 ? E : 64;
        for (int i = 0; i < n; i++) {
            long long v = p[i];
            if (v < 0 || v >= (long long)N) { ok64 = 0; break; }
        }
        g_is64 = ok64;
    }
}

__global__ void k_convert(const void* __restrict__ ei, int E, int N) {
    int i = blockIdx.x * blockDim.x + threadIdx.x;
    if (i >= E) return;
    int s, d;
    if (g_is64) {
        const long long* p = (const long long*)ei;
        s = (int)p[i];
        d = (int)p[E + i];
    } else {
        const int* p = (const int*)ei;
        s = p[i];
        d = p[E + i];
    }
    s = s < 0 ? 0 : (s >= N ? N - 1 : s);
    d = d < 0 ? 0 : (d >= N ? N - 1 : d);
    g_src32[i] = s;
    g_dst32[i] = d;
}

// ---------------- CSR build ------------------------------------------------
__global__ void k_init_deg(int n) {
    int i = blockIdx.x * blockDim.x + threadIdx.x;
    if (i < n) g_deg[i] = 1;   // self loop
}

__global__ void k_count(int E) {
    int i = blockIdx.x * blockDim.x + threadIdx.x;
    if (i < E) atomicAdd(&g_deg[g_dst32[i]], 1);
}

__global__ void k_scan(int n) {
    __shared__ int s[1024];
    int t = threadIdx.x;
    int chunk = (n + 1023) >> 10;
    int b = t * chunk;
    int e = min(b + chunk, n);
    int sum = 0;
    for (int i = b; i < e; i++) sum += g_deg[i];
    s[t] = sum;
    __syncthreads();
    for (int off = 1; off < 1024; off <<= 1) {
        int v = (t >= off) ? s[t - off] : 0;
        __syncthreads();
        s[t] += v;
        __syncthreads();
    }
    int run = (t == 0) ? 0 : s[t - 1];
    for (int i = b; i < e; i++) { g_rowptr[i] = run; run += g_deg[i]; }
    if (t == 1023) g_rowptr[n] = s[1023];
}

__global__ void k_selfloop(int n) {
    int i = blockIdx.x * blockDim.x + threadIdx.x;
    if (i < n) {
        int r = g_rowptr[i];
        g_esrc[r] = i;          // self loop placed first
        g_cursor[i] = r + 1;
    }
}

__global__ void k_scatter(int E) {
    int i = blockIdx.x * blockDim.x + threadIdx.x;
    if (i < E) {
        int d = g_dst32[i];
        int p = atomicAdd(&g_cursor[d], 1);
        g_esrc[p] = g_src32[i];
    }
}

// ---------------- W1 pre-split: fp32 [k][n] -> bf16 hi/lo [n][k] ------------
__global__ void k_prepw(const float* __restrict__ W1) {
    int i = blockIdx.x * blockDim.x + threadIdx.x;
    if (i >= F_IN * HC) return;
    int k = i >> 8;        // row in W1 (k index), HC=256
    int n = i & 255;       // col in W1 (output channel)
    float v = W1[i];
    unsigned short hb, lb;
    asm("cvt.rn.bf16.f32 %0, %1;" : "=h"(hb) : "f"(v));
    float r = v - __uint_as_float((uint32_t)hb << 16);
    asm("cvt.rn.bf16.f32 %0, %1;" : "=h"(lb) : "f"(r));
    g_w1hi[(size_t)n * F_IN + k] = hb;
    g_w1lo[(size_t)n * F_IN + k] = lb;
}

// ---------------- GEMM1: legacy mma.sync bf16 m16n8k16, 3-term split --------
// h1[M x 256] = x[M x 512] @ W1[512 x 256]; ah*bh + ah*bl + al*bh.
__device__ __forceinline__ void mma16(float4& c, unsigned a0, unsigned a1,
                                      unsigned a2, unsigned a3,
                                      unsigned b0, unsigned b1) {
    asm volatile(
        "mma.sync.aligned.m16n8k16.row.col.f32.bf16.bf16.f32 "
        "{%0,%1,%2,%3}, {%4,%5,%6,%7}, {%8,%9}, {%0,%1,%2,%3};"
        : "+f"(c.x), "+f"(c.y), "+f"(c.z), "+f"(c.w)
        : "r"(a0), "r"(a1), "r"(a2), "r"(a3), "r"(b0), "r"(b1));
}

#define PITCH 136   // smem pitch in words: fragment gathers conflict-free

__global__ __launch_bounds__(256) void k_gemm1_bf(const float* __restrict__ A, int M) {
    // packed bf16x2 tiles, word index kw = k-pair, kw in [0,8)
    __shared__ unsigned As2h[8][PITCH];
    __shared__ unsigned As2l[8][PITCH];
    __shared__ unsigned Bs2h[8][PITCH];
    __shared__ unsigned Bs2l[8][PITCH];

    int t    = threadIdx.x;
    int warp = t >> 5, lane = t & 31;
    int wm   = (warp >> 2) * 64;     // warp M offset (2 warps in M)
    int wn   = (warp & 3) * 32;      // warp N offset (4 warps in N)
    int gq   = lane >> 2;            // group id 0..7
    int tq   = lane & 3;             // thread-in-group 0..3
    int bm   = blockIdx.x * 128;
    int bn   = blockIdx.y * 128;

    const unsigned* w1h = (const unsigned*)g_w1hi;   // [n][256] packed words
    const unsigned* w1l = (const unsigned*)g_w1lo;

    float4 acc[4][4];
#pragma unroll
    for (int i = 0; i < 4; i++)
#pragma unroll
        for (int j = 0; j < 4; j++) acc[i][j] = make_float4(0.f, 0.f, 0.f, 0.f);

    for (int kt = 0; kt < F_IN; kt += 16) {
        // A tile: 128 rows x 16 k fp32 -> bf16 hi/lo packed, k-major
#pragma unroll
        for (int i = 0; i < 2; i++) {
            int idx = t + i * 256;          // 512 float4
            int row = idx >> 2;
            int c4  = (idx & 3) * 4;        // k offset
            int kw  = (idx & 3) * 2;        // word index
            float4 v = make_float4(0.f, 0.f, 0.f, 0.f);
            int gr = bm + row;
            if (gr < M) v = *(const float4*)(A + (size_t)gr * F_IN + kt + c4);
            unsigned ph01, ph23, pl01, pl23;
            asm("cvt.rn.bf16x2.f32 %0, %1, %2;" : "=r"(ph01) : "f"(v.y), "f"(v.x));
            asm("cvt.rn.bf16x2.f32 %0, %1, %2;" : "=r"(ph23) : "f"(v.w), "f"(v.z));
            float r0 = v.x - __uint_as_float(ph01 << 16);
            float r1 = v.y - __uint_as_float(ph01 & 0xffff0000u);
            float r2 = v.z - __uint_as_float(ph23 << 16);
            float r3 = v.w - __uint_as_float(ph23 & 0xffff0000u);
            asm("cvt.rn.bf16x2.f32 %0, %1, %2;" : "=r"(pl01) : "f"(r1), "f"(r0));
            asm("cvt.rn.bf16x2.f32 %0, %1, %2;" : "=r"(pl23) : "f"(r3), "f"(r2));
            As2h[kw][row]     = ph01;
            As2h[kw + 1][row] = ph23;
            As2l[kw][row]     = pl01;
            As2l[kw + 1][row] = pl23;
        }
        // B tile: 128 cols x 16 k packed words from pre-split transposed W1
#pragma unroll
        for (int i = 0; i < 2; i++) {
            int e = t + i * 256;            // 512 uint2 per array
            int col = e >> 2;
            int kw  = (e & 3) * 2;
            size_t gi = (size_t)(bn + col) * 256 + (kt >> 1) + kw;
            uint2 vh = *(const uint2*)(w1h + gi);
            uint2 vl = *(const uint2*)(w1l + gi);
            Bs2h[kw][col]     = vh.x;
            Bs2h[kw + 1][col] = vh.y;
            Bs2l[kw][col]     = vl.x;
            Bs2l[kw + 1][col] = vl.y;
        }
        __syncthreads();

        unsigned ah[4][4], al[4][4], bh[4][2], bl[4][2];
#pragma unroll
        for (int mi = 0; mi < 4; mi++) {
            int m = wm + mi * 16 + gq;
            ah[mi][0] = As2h[tq][m];
            ah[mi][1] = As2h[tq][m + 8];
            ah[mi][2] = As2h[tq + 4][m];
            ah[mi][3] = As2h[tq + 4][m + 8];
            al[mi][0] = As2l[tq][m];
            al[mi][1] = As2l[tq][m + 8];
            al[mi][2] = As2l[tq + 4][m];
            al[mi][3] = As2l[tq + 4][m + 8];
        }
#pragma unroll
        for (int nj = 0; nj < 4; nj++) {
            int n = wn + nj * 8 + gq;
            bh[nj][0] = Bs2h[tq][n];
            bh[nj][1] = Bs2h[tq + 4][n];
            bl[nj][0] = Bs2l[tq][n];
            bl[nj][1] = Bs2l[tq + 4][n];
        }
#pragma unroll
        for (int mi = 0; mi < 4; mi++)
#pragma unroll
            for (int nj = 0; nj < 4; nj++) {
                mma16(acc[mi][nj], ah[mi][0], ah[mi][1], ah[mi][2], ah[mi][3],
                      bl[nj][0], bl[nj][1]);                    // hi*lo
                mma16(acc[mi][nj], al[mi][0], al[mi][1], al[mi][2], al[mi][3],
                      bh[nj][0], bh[nj][1]);                    // lo*hi
                mma16(acc[mi][nj], ah[mi][0], ah[mi][1], ah[mi][2], ah[mi][3],
                      bh[nj][0], bh[nj][1]);                    // hi*hi
            }
        __syncthreads();
    }

    // epilogue: c0,c1 (row g, cols 2tq,2tq+1), c2,c3 (row g+8)
#pragma unroll
    for (int mi = 0; mi < 4; mi++) {
        int row0 = bm + wm + mi * 16 + gq;
        int row1 = row0 + 8;
#pragma unroll
        for (int nj = 0; nj < 4; nj++) {
            int col = bn + wn + nj * 8 + tq * 2;
            if (row0 < M)
                *(float2*)(g_h1 + (size_t)row0 * HC + col) =
                    make_float2(acc[mi][nj].x, acc[mi][nj].y);
            if (row1 < M)
                *(float2*)(g_h1 + (size_t)row1 * HC + col) =
                    make_float2(acc[mi][nj].z, acc[mi][nj].w);
        }
    }
}

// ---------------- attention coefficients layer 1 ---------------------------
__global__ void k_attn1(const float* __restrict__ att_src,
                        const float* __restrict__ att_dst, int N) {
    int warp = (blockIdx.x * blockDim.x + threadIdx.x) >> 5;
    int lane = threadIdx.x & 31;
    if (warp >= N) return;
    const float4* hp = (const float4*)(g_h1 + (size_t)warp * HC);
    float4 h0 = hp[lane * 2], h1v = hp[lane * 2 + 1];
    int base = lane * 8;
    float4 s0 = *(const float4*)(att_src + base);
    float4 s1 = *(const float4*)(att_src + base + 4);
    float4 d0 = *(const float4*)(att_dst + base);
    float4 d1 = *(const float4*)(att_dst + base + 4);
    float ps = h0.x * s0.x + h0.y * s0.y + h0.z * s0.z + h0.w * s0.w
             + h1v.x * s1.x + h1v.y * s1.y + h1v.z * s1.z + h1v.w * s1.w;
    float pd = h0.x * d0.x + h0.y * d0.y + h0.z * d0.z + h0.w * d0.w
             + h1v.x * d1.x + h1v.y * d1.y + h1v.z * d1.z + h1v.w * d1.w;
#pragma unroll
    for (int o = 4; o; o >>= 1) {
        ps += __shfl_xor_sync(0xffffffffu, ps, o);
        pd += __shfl_xor_sync(0xffffffffu, pd, o);
    }
    if ((lane & 7) == 0) {
        int h = lane >> 3;
        g_asrc1[warp * NH + h] = ps;
        g_adst1[warp * NH + h] = pd;
    }
}

// ---------------- layer-1 aggregation: warp/node, online softmax -----------
__global__ void k_agg1(const float* __restrict__ b1, int N) {
    int node = (blockIdx.x * blockDim.x + threadIdx.x) >> 5;
    int lane = threadIdx.x & 31;
    if (node >= N) return;
    int head = lane >> 3;
    int start = g_rowptr[node], end = g_rowptr[node + 1];
    float ad = g_adst1[node * NH + head];
    float m = NEG_INF, d = 0.f;
    float acc[8];
#pragma unroll
    for (int j = 0; j < 8; j++) acc[j] = 0.f;

    for (int e = start; e < end; e++) {
        int s = g_esrc[e];
        float al = g_asrc1[s * NH + head] + ad;
        al = al > 0.f ? al : 0.2f * al;             // leaky_relu
        float mn = fmaxf(m, al);
        float sc = __expf(m - mn);                  // 0 on first edge
        float w  = __expf(al - mn);
        d = d * sc + w;
        const float4* hp = (const float4*)(g_h1 + (size_t)s * HC) + lane * 2;
        float4 v0 = hp[0], v1 = hp[1];
        acc[0] = acc[0] * sc + w * v0.x;
        acc[1] = acc[1] * sc + w * v0.y;
        acc[2] = acc[2] * sc + w * v0.z;
        acc[3] = acc[3] * sc + w * v0.w;
        acc[4] = acc[4] * sc + w * v1.x;
        acc[5] = acc[5] * sc + w * v1.y;
        acc[6] = acc[6] * sc + w * v1.z;
        acc[7] = acc[7] * sc + w * v1.w;
        m = mn;
    }
    float inv = 1.f / (d + 1e-16f);
    int col = lane * 8;
#pragma unroll
    for (int j = 0; j < 8; j++) {
        float v = acc[j] * inv + __ldg(b1 + col + j);
        acc[j] = v > 0.f ? v : (expf(v) - 1.f);     // elu
    }
    float4* op = (float4*)(g_h2 + (size_t)node * HC + col);
    op[0] = make_float4(acc[0], acc[1], acc[2], acc[3]);
    op[1] = make_float4(acc[4], acc[5], acc[6], acc[7]);
}

// ---------------- GEMM2: h3[M x 40] = h2[M x 256] @ W2[256 x 40] -----------
__global__ __launch_bounds__(256) void k_gemm2(const float* __restrict__ W2, int M) {
    __shared__ float hs[64][65];
    __shared__ float ws[64][OUTC];
    int t = threadIdx.x;
    int bm = blockIdx.x * 64;
    int cg = t & 7;
    int rg = t >> 3;
    float acc[2][5];
#pragma unroll
    for (int r = 0; r < 2; r++)
#pragma unroll
        for (int j = 0; j < 5; j++) acc[r][j] = 0.f;

    for (int kt = 0; kt < HC; kt += 64) {
#pragma unroll
        for (int i = 0; i < 4; i++) {
            int idx = t + i * 256;
            int row = idx >> 4;
            int c4  = (idx & 15) * 4;
            float4 v = make_float4(0.f, 0.f, 0.f, 0.f);
            int gr = bm + row;
            if (gr < M) v = *(const float4*)(g_h2 + (size_t)gr * HC + kt + c4);
            hs[row][c4 + 0] = v.x;
            hs[row][c4 + 1] = v.y;
            hs[row][c4 + 2] = v.z;
            hs[row][c4 + 3] = v.w;
        }
#pragma unroll
        for (int i = 0; i < 10; i++) {
            int idx = t + i * 256;
            int kr = idx / OUTC;
            int c  = idx - kr * OUTC;
            ws[kr][c] = W2[(size_t)(kt + kr) * OUTC + c];
        }
        __syncthreads();
#pragma unroll
        for (int k = 0; k < 64; k++) {
            float h0 = hs[rg * 2][k];
            float h1v = hs[rg * 2 + 1][k];
#pragma unroll
            for (int j = 0; j < 5; j++) {
                float w = ws[k][cg * 5 + j];
                acc[0][j] += h0 * w;
                acc[1][j] += h1v * w;
            }
        }
        __syncthreads();
    }
#pragma unroll
    for (int r = 0; r < 2; r++) {
        int gr = bm + rg * 2 + r;
        if (gr >= M) continue;
#pragma unroll
        for (int j = 0; j < 5; j++)
            g_h3[(size_t)gr * OUTC + cg * 5 + j] = acc[r][j];
    }
}

// ---------------- attention coefficients layer 2 ---------------------------
__global__ void k_attn2(const float* __restrict__ att_src,
                        const float* __restrict__ att_dst, int N) {
    int node = (blockIdx.x * blockDim.x + threadIdx.x) >> 5;
    int lane = threadIdx.x & 31;
    if (node >= N) return;
    const float* hp = g_h3 + (size_t)node * OUTC;
    float ps = hp[lane] * __ldg(att_src + lane);
    float pd = hp[lane] * __ldg(att_dst + lane);
    if (lane < 8) {
        ps += hp[32 + lane] * __ldg(att_src + 32 + lane);
        pd += hp[32 + lane] * __ldg(att_dst + 32 + lane);
    }
#pragma unroll
    for (int o = 16; o; o >>= 1) {
        ps += __shfl_xor_sync(0xffffffffu, ps, o);
        pd += __shfl_xor_sync(0xffffffffu, pd, o);
    }
    if (lane == 0) { g_asrc2[node] = ps; g_adst2[node] = pd; }
}

// ---------------- layer-2 aggregation + bias + log_softmax -----------------
__global__ void k_agg2(const float* __restrict__ b2, float* __restrict__ out, int N) {
    int node = (blockIdx.x * blockDim.x + threadIdx.x) >> 5;
    int lane = threadIdx.x & 31;
    if (node >= N) return;
    int start = g_rowptr[node], end = g_rowptr[node + 1];
    float ad = g_adst2[node];
    float m = NEG_INF, d = 0.f;
    float a0 = 0.f, a1 = 0.f;
    for (int e = start; e < end; e++) {
        int s = g_esrc[e];
        float al = g_asrc2[s] + ad;
        al = al > 0.f ? al : 0.2f * al;
        float mn = fmaxf(m, al);
        float sc = __expf(m - mn);
        float w  = __expf(al - mn);
        d = d * sc + w;
        const float* hp = g_h3 + (size_t)s * OUTC;
        float v0 = hp[lane];
        float v1 = (lane < 8) ? hp[32 + lane] : 0.f;
        a0 = a0 * sc + w * v0;
        a1 = a1 * sc + w * v1;
        m = mn;
    }
    float inv = 1.f / (d + 1e-16f);
    float o0 = a0 * inv + __ldg(b2 + lane);
    float o1 = (lane < 8) ? (a1 * inv + __ldg(b2 + 32 + lane)) : NEG_INF;
    float mx = fmaxf(o0, o1);
#pragma unroll
    for (int o = 16; o; o >>= 1) mx = fmaxf(mx, __shfl_xor_sync(0xffffffffu, mx, o));
    float se = expf(o0 - mx) + ((lane < 8) ? expf(o1 - mx) : 0.f);
#pragma unroll
    for (int o = 16; o; o >>= 1) se += __shfl_xor_sync(0xffffffffu, se, o);
    float L = logf(se);
    float* op = out + (size_t)node * OUTC;
    op[lane] = o0 - mx - L;
    if (lane < 8) op[32 + lane] = o1 - mx - L;
}

// ---------------- launch ----------------------------------------------------
extern "C" void kernel_launch(void* const* d_in, const int* in_sizes, int n_in,
                              void* d_out, int out_size) {
    const float* x   = (const float*)d_in[0];
    const void*  ei  = d_in[1];
    const float* W1  = (const float*)d_in[2];
    const float* as1 = (const float*)d_in[3];
    const float* ad1 = (const float*)d_in[4];
    const float* b1  = (const float*)d_in[5];
    const float* W2  = (const float*)d_in[6];
    const float* as2 = (const float*)d_in[7];
    const float* ad2 = (const float*)d_in[8];
    const float* b2  = (const float*)d_in[9];
    float*       out = (float*)d_out;

    int N = in_sizes[0] / F_IN;
    int E = in_sizes[1] / 2;

    int nb = (N + 255) / 256;
    int eb = (E + 255) / 256;
    int wb = (N + 7) / 8;   // one warp per node, 8 warps per block

    // Edge dtype normalization + CSR by destination (self loops included)
    k_detect<<<1, 32>>>(ei, E, N);
    k_convert<<<eb, 256>>>(ei, E, N);
    k_init_deg<<<nb, 256>>>(N);
    k_count<<<eb, 256>>>(E);
    k_scan<<<1, 1024>>>(N);
    k_selfloop<<<nb, 256>>>(N);
    k_scatter<<<eb, 256>>>(E);

    // Layer 1
    k_prepw<<<(F_IN * HC + 255) / 256, 256>>>(W1);
    dim3 g1((N + 127) / 128, HC / 128);
    k_gemm1_bf<<<g1, 256>>>(x, N);
    k_attn1<<<wb, 256>>>(as1, ad1, N);
    k_agg1<<<wb, 256>>>(b1, N);

    // Layer 2
    k_gemm2<<<(N + 63) / 64, 256>>>(W2, N);
    k_attn2<<<wb, 256>>>(as2, ad2, N);
    k_agg2<<<wb, 256>>>(b2, out, N);
}